// round 2
// baseline (speedup 1.0000x reference)
#include <cuda_runtime.h>

#define N_NODES 50000
#define N_EDGES 1600000
#define D 512   // D_IN == D_OUT == 512

// ---------------- device scratch (no allocations allowed) ----------------
__device__ float g_hidden[(long long)N_NODES * D];   // X @ W
__device__ int   g_rowstart[N_NODES + 1];            // CSR row offsets
__device__ int   g_cursor[N_NODES];                  // counts, then cursors
__device__ int   g_ecol[N_EDGES];                    // bucketed cols
__device__ float g_eval[N_EDGES];                    // bucketed vals
__device__ int   g_idx_is64;                         // 1 if indices are int64

// ---------------- dtype probe -------------------------------------------
// int64 indices in [0,50000) have all odd 32-bit words == 0.
// int32 indices have random node ids at odd words (P(all zero) ~ 0).
__global__ void probe_idx_dtype(const int* __restrict__ er32,
                                const int* __restrict__ ec32) {
    int looks64 = 1;
    for (int i = 0; i < 256; i++) {
        if (er32[2 * i + 1] != 0) { looks64 = 0; break; }
        if (ec32[2 * i + 1] != 0) { looks64 = 0; break; }
    }
    g_idx_is64 = looks64;
}

__device__ __forceinline__ int load_idx(const void* p, int e, int is64) {
    long long v;
    if (is64) v = ((const long long*)p)[e];
    else      v = ((const int*)p)[e];
    // clamp: never allow OOB no matter what
    if (v < 0) v = 0;
    if (v >= N_NODES) v = N_NODES - 1;
    return (int)v;
}

// ---------------- GEMM: hidden = X[N,512] @ W[512,512] -------------------
// 64x64 tile per 256-thread block, 4x4 register tile per thread, BK=16.
__global__ __launch_bounds__(256) void gemm64(const float* __restrict__ X,
                                              const float* __restrict__ W) {
    __shared__ float As[16][64];   // [k][m]
    __shared__ float Bs[16][64];   // [k][n]

    const int brow = blockIdx.y * 64;
    const int bcol = blockIdx.x * 64;
    const int tid  = threadIdx.x;
    const int ty   = tid >> 4;     // 0..15
    const int tx   = tid & 15;     // 0..15

    const int ar  = tid >> 2;          // 0..63
    const int ak  = (tid & 3) << 2;    // 0,4,8,12
    const int arow = brow + ar;
    const int bkr = tid >> 4;          // 0..15
    const int bc  = (tid & 15) << 2;   // 0..60

    float acc[4][4] = {};

    for (int k0 = 0; k0 < D; k0 += 16) {
        float4 a4 = make_float4(0.f, 0.f, 0.f, 0.f);
        if (arow < N_NODES)
            a4 = *(const float4*)(X + (long long)arow * D + k0 + ak);
        As[ak + 0][ar] = a4.x;
        As[ak + 1][ar] = a4.y;
        As[ak + 2][ar] = a4.z;
        As[ak + 3][ar] = a4.w;

        float4 b4 = *(const float4*)(W + (long long)(k0 + bkr) * D + bcol + bc);
        *(float4*)&Bs[bkr][bc] = b4;

        __syncthreads();

        #pragma unroll
        for (int k = 0; k < 16; k++) {
            float4 av = *(const float4*)&As[k][ty << 2];
            float4 bv = *(const float4*)&Bs[k][tx << 2];
            float a[4] = {av.x, av.y, av.z, av.w};
            float b[4] = {bv.x, bv.y, bv.z, bv.w};
            #pragma unroll
            for (int i = 0; i < 4; i++)
                #pragma unroll
                for (int j = 0; j < 4; j++)
                    acc[i][j] += a[i] * b[j];
        }
        __syncthreads();
    }

    #pragma unroll
    for (int i = 0; i < 4; i++) {
        int row = brow + (ty << 2) + i;
        if (row < N_NODES) {
            float4 o = make_float4(acc[i][0], acc[i][1], acc[i][2], acc[i][3]);
            *(float4*)(g_hidden + (long long)row * D + bcol + (tx << 2)) = o;
        }
    }
}

// ---------------- CSR build --------------------------------------------
__global__ void zero_counts() {
    int i = blockIdx.x * blockDim.x + threadIdx.x;
    if (i < N_NODES) g_cursor[i] = 0;
}

__global__ void hist_rows(const void* __restrict__ er) {
    int e = blockIdx.x * blockDim.x + threadIdx.x;
    if (e < N_EDGES) {
        int row = load_idx(er, e, g_idx_is64);
        atomicAdd(&g_cursor[row], 1);
    }
}

// single-block exclusive scan over g_cursor -> g_rowstart, reset cursors
__global__ __launch_bounds__(1024) void scan_counts() {
    __shared__ int sdata[1024];
    __shared__ int carry;
    if (threadIdx.x == 0) carry = 0;
    __syncthreads();

    for (int base = 0; base < N_NODES; base += 1024) {
        int i = base + threadIdx.x;
        int v = (i < N_NODES) ? g_cursor[i] : 0;
        sdata[threadIdx.x] = v;
        __syncthreads();
        for (int off = 1; off < 1024; off <<= 1) {
            int t = (threadIdx.x >= off) ? sdata[threadIdx.x - off] : 0;
            __syncthreads();
            sdata[threadIdx.x] += t;
            __syncthreads();
        }
        int excl = sdata[threadIdx.x] - v + carry;
        if (i < N_NODES) {
            g_rowstart[i] = excl;
            g_cursor[i]   = excl;   // becomes scatter cursor
        }
        __syncthreads();
        if (threadIdx.x == 1023) carry += sdata[1023];
        __syncthreads();
    }
    if (threadIdx.x == 0) g_rowstart[N_NODES] = carry;
}

__global__ void bucket_edges(const float* __restrict__ ev,
                             const void* __restrict__ er,
                             const void* __restrict__ ec) {
    int e = blockIdx.x * blockDim.x + threadIdx.x;
    if (e < N_EDGES) {
        int is64 = g_idx_is64;
        int row = load_idx(er, e, is64);
        int col = load_idx(ec, e, is64);
        int pos = atomicAdd(&g_cursor[row], 1);
        if (pos >= 0 && pos < N_EDGES) {
            g_ecol[pos] = col;
            g_eval[pos] = ev[e];
        }
    }
}

// ---------------- gather SpMM: out[i] = bias + sum val*hidden[col] -------
__global__ __launch_bounds__(128) void gather_spmm(const float* __restrict__ bias,
                                                   float* __restrict__ out) {
    const int node  = blockIdx.x;
    const int start = g_rowstart[node];
    const int end   = g_rowstart[node + 1];

    __shared__ int   s_col[512];
    __shared__ float s_val[512];

    const float4* __restrict__ H4 = (const float4*)g_hidden;
    float4 acc = make_float4(0.f, 0.f, 0.f, 0.f);

    for (int base = start; base < end; base += 512) {
        int cnt = min(end - base, 512);
        for (int i = threadIdx.x; i < cnt; i += 128) {
            s_col[i] = g_ecol[base + i];
            s_val[i] = g_eval[base + i];
        }
        __syncthreads();
        for (int i = 0; i < cnt; i++) {
            float v  = s_val[i];
            float4 h = H4[(long long)s_col[i] * (D / 4) + threadIdx.x];
            acc.x += v * h.x;
            acc.y += v * h.y;
            acc.z += v * h.z;
            acc.w += v * h.w;
        }
        __syncthreads();
    }

    float4 b = ((const float4*)bias)[threadIdx.x];
    acc.x += b.x; acc.y += b.y; acc.z += b.z; acc.w += b.w;
    ((float4*)out)[(long long)node * (D / 4) + threadIdx.x] = acc;
}

// ---------------- launcher ----------------------------------------------
extern "C" void kernel_launch(void* const* d_in, const int* in_sizes, int n_in,
                              void* d_out, int out_size) {
    const float* x    = (const float*)d_in[0];   // [50000,512]
    const float* w    = (const float*)d_in[1];   // [512,512]
    const float* bias = (const float*)d_in[2];   // [1,512]
    const float* ev   = (const float*)d_in[3];   // [E]
    const void*  er   = d_in[4];                 // [E] int32 or int64
    const void*  ec   = d_in[5];                 // [E] int32 or int64
    float* out = (float*)d_out;                  // [50000,512]

    probe_idx_dtype<<<1, 1>>>((const int*)er, (const int*)ec);

    // 1) hidden = X @ W
    dim3 ggrid(D / 64, (N_NODES + 63) / 64);
    gemm64<<<ggrid, 256>>>(x, w);

    // 2) CSR build
    zero_counts<<<(N_NODES + 255) / 256, 256>>>();
    hist_rows<<<(N_EDGES + 255) / 256, 256>>>(er);
    scan_counts<<<1, 1024>>>();
    bucket_edges<<<(N_EDGES + 255) / 256, 256>>>(ev, er, ec);

    // 3) gather SpMM + bias
    gather_spmm<<<N_NODES, 128>>>(bias, out);
}

// round 3
// speedup vs baseline: 1.5571x; 1.5571x over previous
#include <cuda_runtime.h>
#include <cuda_bf16.h>
#include <cstdint>

#define N_NODES 50000
#define N_EDGES 1600000
#define D 512

// ---------------- device scratch ----------------
__device__ float        g_hidden[(long long)N_NODES * D];
__device__ __nv_bfloat16 g_xhi[(long long)N_NODES * D];
__device__ __nv_bfloat16 g_xlo[(long long)N_NODES * D];
__device__ __nv_bfloat16 g_wThi[D * D];   // [n][k]
__device__ __nv_bfloat16 g_wTlo[D * D];
__device__ int   g_rowstart[N_NODES + 1];
__device__ int   g_cursor[N_NODES];
__device__ int2  g_epack[N_EDGES];        // (col, val-as-int)
__device__ int   g_idx_is64;

// ---------------- dtype probe ----------------
__global__ void probe_idx_dtype(const int* __restrict__ er32,
                                const int* __restrict__ ec32) {
    int looks64 = 1;
    for (int i = 0; i < 256; i++) {
        if (er32[2 * i + 1] != 0) { looks64 = 0; break; }
        if (ec32[2 * i + 1] != 0) { looks64 = 0; break; }
    }
    g_idx_is64 = looks64;
}

__device__ __forceinline__ int load_idx(const void* p, int e, int is64) {
    long long v;
    if (is64) v = ((const long long*)p)[e];
    else      v = ((const int*)p)[e];
    if (v < 0) v = 0;
    if (v >= N_NODES) v = N_NODES - 1;
    return (int)v;
}

// ---------------- bf16 split kernels ----------------
__global__ void split_w(const float* __restrict__ w) {
    int idx = blockIdx.x * blockDim.x + threadIdx.x;   // over 512*512
    if (idx >= D * D) return;
    int k = idx >> 9, n = idx & 511;
    float v = w[idx];                 // w[k][n]
    __nv_bfloat16 hi = __float2bfloat16(v);
    float lo = v - __bfloat162float(hi);
    g_wThi[n * D + k] = hi;
    g_wTlo[n * D + k] = __float2bfloat16(lo);
}

__global__ void split_x(const float* __restrict__ x) {
    long long i = (long long)(blockIdx.x * blockDim.x + threadIdx.x) * 4;
    if (i >= (long long)N_NODES * D) return;
    float4 v = *(const float4*)(x + i);
    __nv_bfloat16 h0 = __float2bfloat16(v.x);
    __nv_bfloat16 h1 = __float2bfloat16(v.y);
    __nv_bfloat16 h2 = __float2bfloat16(v.z);
    __nv_bfloat16 h3 = __float2bfloat16(v.w);
    __nv_bfloat16 l0 = __float2bfloat16(v.x - __bfloat162float(h0));
    __nv_bfloat16 l1 = __float2bfloat16(v.y - __bfloat162float(h1));
    __nv_bfloat16 l2 = __float2bfloat16(v.z - __bfloat162float(h2));
    __nv_bfloat16 l3 = __float2bfloat16(v.w - __bfloat162float(h3));
    __nv_bfloat162* ph = (__nv_bfloat162*)(g_xhi + i);
    __nv_bfloat162* pl = (__nv_bfloat162*)(g_xlo + i);
    ph[0] = __nv_bfloat162(h0, h1); ph[1] = __nv_bfloat162(h2, h3);
    pl[0] = __nv_bfloat162(l0, l1); pl[1] = __nv_bfloat162(l2, l3);
}

// ---------------- tensor-core GEMM ----------------
// hidden = x @ w = (xhi+xlo)@(whi+wlo) ~= xhi@whi + xhi@wlo + xlo@whi
// Block tile 128x128, BK=32, 8 warps (2m x 4n), warp tile 64x32, double buffer.

#define BK 32
#define ROWPAD 40                 // bf16 per smem row (80 B, 16B-aligned, conflict-free)
#define SA (128 * ROWPAD)         // bf16 per matrix per stage

__device__ __forceinline__ void cpa16(uint32_t dst, const void* src) {
    asm volatile("cp.async.cg.shared.global [%0], [%1], 16;\n" :: "r"(dst), "l"(src));
}
__device__ __forceinline__ void cpa_commit() {
    asm volatile("cp.async.commit_group;\n");
}
template <int N>
__device__ __forceinline__ void cpa_wait() {
    asm volatile("cp.async.wait_group %0;\n" :: "n"(N));
}

__device__ __forceinline__ void ldsm_x4(uint32_t* r, uint32_t addr) {
    asm volatile("ldmatrix.sync.aligned.m8n8.x4.shared.b16 {%0,%1,%2,%3}, [%4];\n"
                 : "=r"(r[0]), "=r"(r[1]), "=r"(r[2]), "=r"(r[3]) : "r"(addr));
}
__device__ __forceinline__ void ldsm_x2(uint32_t* r, uint32_t addr) {
    asm volatile("ldmatrix.sync.aligned.m8n8.x2.shared.b16 {%0,%1}, [%2];\n"
                 : "=r"(r[0]), "=r"(r[1]) : "r"(addr));
}
__device__ __forceinline__ void mma16816(float* c, const uint32_t* a, const uint32_t* b) {
    asm volatile("mma.sync.aligned.m16n8k16.row.col.f32.bf16.bf16.f32 "
                 "{%0,%1,%2,%3}, {%4,%5,%6,%7}, {%8,%9}, {%0,%1,%2,%3};\n"
                 : "+f"(c[0]), "+f"(c[1]), "+f"(c[2]), "+f"(c[3])
                 : "r"(a[0]), "r"(a[1]), "r"(a[2]), "r"(a[3]), "r"(b[0]), "r"(b[1]));
}

__global__ __launch_bounds__(256) void gemm_bf16split() {
    extern __shared__ __nv_bfloat16 smem[];
    __nv_bfloat16* sAhi = smem;
    __nv_bfloat16* sAlo = smem + 2 * SA;
    __nv_bfloat16* sBhi = smem + 4 * SA;
    __nv_bfloat16* sBlo = smem + 6 * SA;

    const int tid  = threadIdx.x;
    const int lane = tid & 31;
    const int wid  = tid >> 5;
    const int warp_m = wid & 1;        // 0..1
    const int warp_n = wid >> 1;       // 0..3
    const int brow = blockIdx.y * 128;
    const int bcol = blockIdx.x * 128;

    // cp.async mapping: 2 threads per row, 32B each
    const int lrow  = tid >> 1;        // 0..127
    const int kloc  = (tid & 1) * 16;  // bf16 offset in 32-wide k tile

    int arow = brow + lrow; if (arow >= N_NODES) arow = N_NODES - 1;
    const int bn = bcol + lrow;

    const __nv_bfloat16* srcAh = g_xhi + (long long)arow * D;
    const __nv_bfloat16* srcAl = g_xlo + (long long)arow * D;
    const __nv_bfloat16* srcBh = g_wThi + bn * D;
    const __nv_bfloat16* srcBl = g_wTlo + bn * D;

    const int dstoff = lrow * ROWPAD + kloc;   // bf16 units

    float acc[4][4][4];
    #pragma unroll
    for (int i = 0; i < 4; i++)
        #pragma unroll
        for (int j = 0; j < 4; j++)
            #pragma unroll
            for (int c = 0; c < 4; c++) acc[i][j][c] = 0.f;

    const int NK = D / BK;   // 16

    auto issue_stage = [&](int kt, int st) {
        int k0 = kt * BK + kloc;
        uint32_t dA_hi = (uint32_t)__cvta_generic_to_shared(sAhi + st * SA + dstoff);
        uint32_t dA_lo = (uint32_t)__cvta_generic_to_shared(sAlo + st * SA + dstoff);
        uint32_t dB_hi = (uint32_t)__cvta_generic_to_shared(sBhi + st * SA + dstoff);
        uint32_t dB_lo = (uint32_t)__cvta_generic_to_shared(sBlo + st * SA + dstoff);
        cpa16(dA_hi,      srcAh + k0);
        cpa16(dA_hi + 16, srcAh + k0 + 8);
        cpa16(dA_lo,      srcAl + k0);
        cpa16(dA_lo + 16, srcAl + k0 + 8);
        cpa16(dB_hi,      srcBh + k0);
        cpa16(dB_hi + 16, srcBh + k0 + 8);
        cpa16(dB_lo,      srcBl + k0);
        cpa16(dB_lo + 16, srcBl + k0 + 8);
        cpa_commit();
    };

    issue_stage(0, 0);

    for (int kt = 0; kt < NK; kt++) {
        int st = kt & 1;
        if (kt + 1 < NK) { issue_stage(kt + 1, st ^ 1); cpa_wait<1>(); }
        else             { cpa_wait<0>(); }
        __syncthreads();

        #pragma unroll
        for (int kk = 0; kk < 2; kk++) {   // two k16 slices in BK=32
            uint32_t afh[4][4], afl[4][4];
            uint32_t bfh[4][2], bfl[4][2];

            const int arow_t = warp_m * 64 + (lane & 15);
            const int akoff  = kk * 16 + (lane >> 4) * 8;
            #pragma unroll
            for (int mt = 0; mt < 4; mt++) {
                int off = st * SA + (arow_t + mt * 16) * ROWPAD + akoff;
                ldsm_x4(afh[mt], (uint32_t)__cvta_generic_to_shared(sAhi + off));
                ldsm_x4(afl[mt], (uint32_t)__cvta_generic_to_shared(sAlo + off));
            }
            const int brow_t = warp_n * 32 + (lane & 7);
            const int bkoff  = kk * 16 + ((lane >> 3) & 1) * 8;
            #pragma unroll
            for (int nt = 0; nt < 4; nt++) {
                int off = st * SA + (brow_t + nt * 8) * ROWPAD + bkoff;
                ldsm_x2(bfh[nt], (uint32_t)__cvta_generic_to_shared(sBhi + off));
                ldsm_x2(bfl[nt], (uint32_t)__cvta_generic_to_shared(sBlo + off));
            }

            #pragma unroll
            for (int mt = 0; mt < 4; mt++)
                #pragma unroll
                for (int nt = 0; nt < 4; nt++) {
                    mma16816(acc[mt][nt], afh[mt], bfh[nt]);
                    mma16816(acc[mt][nt], afh[mt], bfl[nt]);
                    mma16816(acc[mt][nt], afl[mt], bfh[nt]);
                }
        }
        __syncthreads();
    }

    // epilogue: c-frag layout of m16n8k16
    #pragma unroll
    for (int mt = 0; mt < 4; mt++) {
        int row0 = brow + warp_m * 64 + mt * 16 + (lane >> 2);
        #pragma unroll
        for (int nt = 0; nt < 4; nt++) {
            int col = bcol + warp_n * 32 + nt * 8 + (lane & 3) * 2;
            if (row0 < N_NODES)
                *(float2*)(g_hidden + (long long)row0 * D + col) =
                    make_float2(acc[mt][nt][0], acc[mt][nt][1]);
            if (row0 + 8 < N_NODES)
                *(float2*)(g_hidden + (long long)(row0 + 8) * D + col) =
                    make_float2(acc[mt][nt][2], acc[mt][nt][3]);
        }
    }
}

// ---------------- CSR build ----------------
__global__ void zero_counts() {
    int i = blockIdx.x * blockDim.x + threadIdx.x;
    if (i < N_NODES) g_cursor[i] = 0;
}

__global__ void hist_rows(const void* __restrict__ er) {
    int e = blockIdx.x * blockDim.x + threadIdx.x;
    if (e < N_EDGES) {
        int row = load_idx(er, e, g_idx_is64);
        atomicAdd(&g_cursor[row], 1);
    }
}

__global__ __launch_bounds__(1024) void scan_counts() {
    __shared__ int sdata[1024];
    __shared__ int carry;
    if (threadIdx.x == 0) carry = 0;
    __syncthreads();
    for (int base = 0; base < N_NODES; base += 1024) {
        int i = base + threadIdx.x;
        int v = (i < N_NODES) ? g_cursor[i] : 0;
        sdata[threadIdx.x] = v;
        __syncthreads();
        for (int off = 1; off < 1024; off <<= 1) {
            int t = (threadIdx.x >= off) ? sdata[threadIdx.x - off] : 0;
            __syncthreads();
            sdata[threadIdx.x] += t;
            __syncthreads();
        }
        int excl = sdata[threadIdx.x] - v + carry;
        if (i < N_NODES) {
            g_rowstart[i] = excl;
            g_cursor[i]   = excl;
        }
        __syncthreads();
        if (threadIdx.x == 1023) carry += sdata[1023];
        __syncthreads();
    }
    if (threadIdx.x == 0) g_rowstart[N_NODES] = carry;
}

__global__ void bucket_edges(const float* __restrict__ ev,
                             const void* __restrict__ er,
                             const void* __restrict__ ec) {
    int e = blockIdx.x * blockDim.x + threadIdx.x;
    if (e < N_EDGES) {
        int is64 = g_idx_is64;
        int row = load_idx(er, e, is64);
        int col = load_idx(ec, e, is64);
        int pos = atomicAdd(&g_cursor[row], 1);
        if (pos >= 0 && pos < N_EDGES)
            g_epack[pos] = make_int2(col, __float_as_int(ev[e]));
    }
}

// ---------------- gather SpMM ----------------
__global__ __launch_bounds__(128) void gather_spmm(const float* __restrict__ bias,
                                                   float* __restrict__ out) {
    const int node  = blockIdx.x;
    const int start = g_rowstart[node];
    const int end   = g_rowstart[node + 1];

    __shared__ int2 s_e[512];

    const float4* __restrict__ H4 = (const float4*)g_hidden;
    float4 acc = make_float4(0.f, 0.f, 0.f, 0.f);

    for (int base = start; base < end; base += 512) {
        int cnt = min(end - base, 512);
        for (int i = threadIdx.x; i < cnt; i += 128)
            s_e[i] = g_epack[base + i];
        __syncthreads();
        for (int i = 0; i < cnt; i++) {
            int2 p = s_e[i];
            float v = __int_as_float(p.y);
            float4 h = H4[(long long)p.x * (D / 4) + threadIdx.x];
            acc.x += v * h.x;
            acc.y += v * h.y;
            acc.z += v * h.z;
            acc.w += v * h.w;
        }
        __syncthreads();
    }

    float4 b = ((const float4*)bias)[threadIdx.x];
    acc.x += b.x; acc.y += b.y; acc.z += b.z; acc.w += b.w;
    ((float4*)out)[(long long)node * (D / 4) + threadIdx.x] = acc;
}

// ---------------- launcher ----------------
extern "C" void kernel_launch(void* const* d_in, const int* in_sizes, int n_in,
                              void* d_out, int out_size) {
    const float* x    = (const float*)d_in[0];
    const float* w    = (const float*)d_in[1];
    const float* bias = (const float*)d_in[2];
    const float* ev   = (const float*)d_in[3];
    const void*  er   = d_in[4];
    const void*  ec   = d_in[5];
    float* out = (float*)d_out;

    probe_idx_dtype<<<1, 1>>>((const int*)er, (const int*)ec);

    // split into bf16 hi/lo
    split_w<<<(D * D + 255) / 256, 256>>>(w);
    split_x<<<(N_NODES * D / 4 + 255) / 256, 256>>>(x);

    // GEMM on tensor pipe
    static const int SMEM_BYTES = 8 * SA * (int)sizeof(__nv_bfloat16); // 81920
    cudaFuncSetAttribute(gemm_bf16split,
                         cudaFuncAttributeMaxDynamicSharedMemorySize, SMEM_BYTES);
    dim3 ggrid(D / 128, (N_NODES + 127) / 128);
    gemm_bf16split<<<ggrid, 256, SMEM_BYTES>>>();

    // CSR build
    zero_counts<<<(N_NODES + 255) / 256, 256>>>();
    hist_rows<<<(N_EDGES + 255) / 256, 256>>>(er);
    scan_counts<<<1, 1024>>>();
    bucket_edges<<<(N_EDGES + 255) / 256, 256>>>(ev, er, ec);

    // gather SpMM + bias
    gather_spmm<<<N_NODES, 128>>>(bias, out);
}

// round 5
// speedup vs baseline: 1.8011x; 1.1567x over previous
#include <cuda_runtime.h>
#include <cuda_bf16.h>
#include <cstdint>

#define N_NODES 50000
#define N_EDGES 1600000
#define D 512

// ---------------- device scratch ----------------
__device__ float         g_hidden[(long long)N_NODES * D];
__device__ __nv_bfloat16 g_xhi[(long long)N_NODES * D];
__device__ __nv_bfloat16 g_xlo[(long long)N_NODES * D];
__device__ __nv_bfloat16 g_wThi[D * D];   // [n][k]
__device__ __nv_bfloat16 g_wTlo[D * D];
__device__ int   g_rowstart[N_NODES + 1];
__device__ int   g_cursor[N_NODES];
__device__ int   g_blocksum[64];
__device__ int2  g_epack[N_EDGES];
__device__ int   g_idx_is64;

// ---------------- dtype probe + zero counts ----------------
__global__ void probe_zero(const int* __restrict__ er32, const int* __restrict__ ec32) {
    int i = blockIdx.x * blockDim.x + threadIdx.x;
    if (i < N_NODES) g_cursor[i] = 0;
    if (i == 0) {
        int looks64 = 1;
        for (int j = 0; j < 256; j++) {
            if (er32[2 * j + 1] != 0) { looks64 = 0; break; }
            if (ec32[2 * j + 1] != 0) { looks64 = 0; break; }
        }
        g_idx_is64 = looks64;
    }
}

__device__ __forceinline__ int load_idx(const void* p, int e, int is64) {
    long long v;
    if (is64) v = ((const long long*)p)[e];
    else      v = ((const int*)p)[e];
    if (v < 0) v = 0;
    if (v >= N_NODES) v = N_NODES - 1;
    return (int)v;
}

// ---------------- bf16 splits ----------------
__global__ void split_w(const float* __restrict__ w) {
    int idx = blockIdx.x * blockDim.x + threadIdx.x;
    if (idx >= D * D) return;
    int k = idx >> 9, n = idx & 511;
    float v = w[idx];
    __nv_bfloat16 hi = __float2bfloat16(v);
    g_wThi[n * D + k] = hi;
    g_wTlo[n * D + k] = __float2bfloat16(v - __bfloat162float(hi));
}

__global__ void split_x(const float* __restrict__ x) {
    long long i = (long long)(blockIdx.x * blockDim.x + threadIdx.x) * 4;
    if (i >= (long long)N_NODES * D) return;
    float4 v = *(const float4*)(x + i);
    __nv_bfloat16 h0 = __float2bfloat16(v.x), h1 = __float2bfloat16(v.y);
    __nv_bfloat16 h2 = __float2bfloat16(v.z), h3 = __float2bfloat16(v.w);
    __nv_bfloat16 l0 = __float2bfloat16(v.x - __bfloat162float(h0));
    __nv_bfloat16 l1 = __float2bfloat16(v.y - __bfloat162float(h1));
    __nv_bfloat16 l2 = __float2bfloat16(v.z - __bfloat162float(h2));
    __nv_bfloat16 l3 = __float2bfloat16(v.w - __bfloat162float(h3));
    __nv_bfloat162* ph = (__nv_bfloat162*)(g_xhi + i);
    __nv_bfloat162* pl = (__nv_bfloat162*)(g_xlo + i);
    ph[0] = __nv_bfloat162(h0, h1); ph[1] = __nv_bfloat162(h2, h3);
    pl[0] = __nv_bfloat162(l0, l1); pl[1] = __nv_bfloat162(l2, l3);
}

// ---------------- tensor-core GEMM (mma.sync, 3-term bf16 split) ----------
#define BK 32
#define ROWPAD 40
#define SA (128 * ROWPAD)

__device__ __forceinline__ void cpa16(uint32_t dst, const void* src) {
    asm volatile("cp.async.cg.shared.global [%0], [%1], 16;\n" :: "r"(dst), "l"(src));
}
__device__ __forceinline__ void cpa_commit() { asm volatile("cp.async.commit_group;\n"); }
template <int N>
__device__ __forceinline__ void cpa_wait() { asm volatile("cp.async.wait_group %0;\n" :: "n"(N)); }

__device__ __forceinline__ void ldsm_x4(uint32_t* r, uint32_t addr) {
    asm volatile("ldmatrix.sync.aligned.m8n8.x4.shared.b16 {%0,%1,%2,%3}, [%4];\n"
                 : "=r"(r[0]), "=r"(r[1]), "=r"(r[2]), "=r"(r[3]) : "r"(addr));
}
__device__ __forceinline__ void ldsm_x2(uint32_t* r, uint32_t addr) {
    asm volatile("ldmatrix.sync.aligned.m8n8.x2.shared.b16 {%0,%1}, [%2];\n"
                 : "=r"(r[0]), "=r"(r[1]) : "r"(addr));
}
__device__ __forceinline__ void mma16816(float* c, const uint32_t* a, const uint32_t* b) {
    asm volatile("mma.sync.aligned.m16n8k16.row.col.f32.bf16.bf16.f32 "
                 "{%0,%1,%2,%3}, {%4,%5,%6,%7}, {%8,%9}, {%0,%1,%2,%3};\n"
                 : "+f"(c[0]), "+f"(c[1]), "+f"(c[2]), "+f"(c[3])
                 : "r"(a[0]), "r"(a[1]), "r"(a[2]), "r"(a[3]), "r"(b[0]), "r"(b[1]));
}

__global__ __launch_bounds__(256, 2) void gemm_bf16split() {
    extern __shared__ __nv_bfloat16 smem[];
    __nv_bfloat16* sAhi = smem;
    __nv_bfloat16* sAlo = smem + 2 * SA;
    __nv_bfloat16* sBhi = smem + 4 * SA;
    __nv_bfloat16* sBlo = smem + 6 * SA;

    const int tid  = threadIdx.x;
    const int lane = tid & 31;
    const int wid  = tid >> 5;
    const int warp_m = wid & 1;
    const int warp_n = wid >> 1;
    const int brow = blockIdx.y * 128;
    const int bcol = blockIdx.x * 128;

    const int lrow  = tid >> 1;
    const int kloc  = (tid & 1) * 16;

    int arow = brow + lrow; if (arow >= N_NODES) arow = N_NODES - 1;
    const int bn = bcol + lrow;

    const __nv_bfloat16* srcAh = g_xhi + (long long)arow * D;
    const __nv_bfloat16* srcAl = g_xlo + (long long)arow * D;
    const __nv_bfloat16* srcBh = g_wThi + bn * D;
    const __nv_bfloat16* srcBl = g_wTlo + bn * D;

    const int dstoff = lrow * ROWPAD + kloc;

    float acc[4][4][4];
    #pragma unroll
    for (int i = 0; i < 4; i++)
        #pragma unroll
        for (int j = 0; j < 4; j++)
            #pragma unroll
            for (int c = 0; c < 4; c++) acc[i][j][c] = 0.f;

    const int NK = D / BK;   // 16

    auto issue_stage = [&](int kt, int st) {
        int k0 = kt * BK + kloc;
        uint32_t dA_hi = (uint32_t)__cvta_generic_to_shared(sAhi + st * SA + dstoff);
        uint32_t dA_lo = (uint32_t)__cvta_generic_to_shared(sAlo + st * SA + dstoff);
        uint32_t dB_hi = (uint32_t)__cvta_generic_to_shared(sBhi + st * SA + dstoff);
        uint32_t dB_lo = (uint32_t)__cvta_generic_to_shared(sBlo + st * SA + dstoff);
        cpa16(dA_hi,      srcAh + k0);
        cpa16(dA_hi + 16, srcAh + k0 + 8);
        cpa16(dA_lo,      srcAl + k0);
        cpa16(dA_lo + 16, srcAl + k0 + 8);
        cpa16(dB_hi,      srcBh + k0);
        cpa16(dB_hi + 16, srcBh + k0 + 8);
        cpa16(dB_lo,      srcBl + k0);
        cpa16(dB_lo + 16, srcBl + k0 + 8);
        cpa_commit();
    };

    issue_stage(0, 0);

    for (int kt = 0; kt < NK; kt++) {
        int st = kt & 1;
        if (kt + 1 < NK) { issue_stage(kt + 1, st ^ 1); cpa_wait<1>(); }
        else             { cpa_wait<0>(); }
        __syncthreads();

        #pragma unroll
        for (int kk = 0; kk < 2; kk++) {
            uint32_t afh[4][4], afl[4][4];
            uint32_t bfh[4][2], bfl[4][2];

            const int arow_t = warp_m * 64 + (lane & 15);
            const int akoff  = kk * 16 + (lane >> 4) * 8;
            #pragma unroll
            for (int mt = 0; mt < 4; mt++) {
                int off = st * SA + (arow_t + mt * 16) * ROWPAD + akoff;
                ldsm_x4(afh[mt], (uint32_t)__cvta_generic_to_shared(sAhi + off));
                ldsm_x4(afl[mt], (uint32_t)__cvta_generic_to_shared(sAlo + off));
            }
            const int brow_t = warp_n * 32 + (lane & 7);
            const int bkoff  = kk * 16 + ((lane >> 3) & 1) * 8;
            #pragma unroll
            for (int nt = 0; nt < 4; nt++) {
                int off = st * SA + (brow_t + nt * 8) * ROWPAD + bkoff;
                ldsm_x2(bfh[nt], (uint32_t)__cvta_generic_to_shared(sBhi + off));
                ldsm_x2(bfl[nt], (uint32_t)__cvta_generic_to_shared(sBlo + off));
            }

            #pragma unroll
            for (int mt = 0; mt < 4; mt++)
                #pragma unroll
                for (int nt = 0; nt < 4; nt++) {
                    mma16816(acc[mt][nt], afh[mt], bfh[nt]);
                    mma16816(acc[mt][nt], afh[mt], bfl[nt]);
                    mma16816(acc[mt][nt], afl[mt], bfh[nt]);
                }
        }
        __syncthreads();
    }

    #pragma unroll
    for (int mt = 0; mt < 4; mt++) {
        int row0 = brow + warp_m * 64 + mt * 16 + (lane >> 2);
        #pragma unroll
        for (int nt = 0; nt < 4; nt++) {
            int col = bcol + warp_n * 32 + nt * 8 + (lane & 3) * 2;
            if (row0 < N_NODES)
                *(float2*)(g_hidden + (long long)row0 * D + col) =
                    make_float2(acc[mt][nt][0], acc[mt][nt][1]);
            if (row0 + 8 < N_NODES)
                *(float2*)(g_hidden + (long long)(row0 + 8) * D + col) =
                    make_float2(acc[mt][nt][2], acc[mt][nt][3]);
        }
    }
}

// ---------------- CSR build ----------------
__global__ void hist_rows(const void* __restrict__ er) {
    int e = blockIdx.x * blockDim.x + threadIdx.x;
    if (e < N_EDGES) atomicAdd(&g_cursor[load_idx(er, e, g_idx_is64)], 1);
}

#define SCAN_BLOCKS ((N_NODES + 1023) / 1024)

__global__ __launch_bounds__(1024) void scan_local() {
    __shared__ int sdata[1024];
    int b = blockIdx.x, t = threadIdx.x;
    int i = b * 1024 + t;
    int v = (i < N_NODES) ? g_cursor[i] : 0;
    sdata[t] = v;
    __syncthreads();
    for (int off = 1; off < 1024; off <<= 1) {
        int tv = (t >= off) ? sdata[t - off] : 0;
        __syncthreads();
        sdata[t] += tv;
        __syncthreads();
    }
    if (i < N_NODES) g_rowstart[i] = sdata[t] - v;     // local exclusive
    if (t == 1023) g_blocksum[b] = sdata[1023];
}

__global__ void scan_offsets() {
    if (threadIdx.x == 0) {
        int run = 0;
        for (int j = 0; j < SCAN_BLOCKS; j++) {
            int s = g_blocksum[j];
            g_blocksum[j] = run;
            run += s;
        }
        g_rowstart[N_NODES] = run;
    }
}

__global__ __launch_bounds__(1024) void scan_add() {
    int i = blockIdx.x * 1024 + threadIdx.x;
    if (i < N_NODES) {
        int v = g_rowstart[i] + g_blocksum[blockIdx.x];
        g_rowstart[i] = v;
        g_cursor[i]   = v;
    }
}

__global__ void bucket_edges(const float* __restrict__ ev,
                             const void* __restrict__ er,
                             const void* __restrict__ ec) {
    int e = blockIdx.x * blockDim.x + threadIdx.x;
    if (e < N_EDGES) {
        int is64 = g_idx_is64;
        int row = load_idx(er, e, is64);
        int col = load_idx(ec, e, is64);
        int pos = atomicAdd(&g_cursor[row], 1);
        if (pos >= 0 && pos < N_EDGES)
            g_epack[pos] = make_int2(col, __float_as_int(ev[e]));
    }
}

// ---------------- gather SpMM ----------------
__global__ __launch_bounds__(128) void gather_spmm(const float* __restrict__ bias,
                                                   float* __restrict__ out) {
    const int node  = blockIdx.x;
    const int start = g_rowstart[node];
    const int end   = g_rowstart[node + 1];

    __shared__ int2 s_e[512];
    const float4* __restrict__ H4 = (const float4*)g_hidden;
    float4 acc = make_float4(0.f, 0.f, 0.f, 0.f);

    for (int base = start; base < end; base += 512) {
        int cnt = min(end - base, 512);
        for (int i = threadIdx.x; i < cnt; i += 128)
            s_e[i] = g_epack[base + i];
        __syncthreads();
        for (int i = 0; i < cnt; i++) {
            int2 p = s_e[i];
            float v = __int_as_float(p.y);
            float4 h = H4[(long long)p.x * (D / 4) + threadIdx.x];
            acc.x += v * h.x; acc.y += v * h.y;
            acc.z += v * h.z; acc.w += v * h.w;
        }
        __syncthreads();
    }

    float4 b = ((const float4*)bias)[threadIdx.x];
    acc.x += b.x; acc.y += b.y; acc.z += b.z; acc.w += b.w;
    ((float4*)out)[(long long)node * (D / 4) + threadIdx.x] = acc;
}

// ---------------- launcher ----------------
extern "C" void kernel_launch(void* const* d_in, const int* in_sizes, int n_in,
                              void* d_out, int out_size) {
    const float* x    = (const float*)d_in[0];
    const float* w    = (const float*)d_in[1];
    const float* bias = (const float*)d_in[2];
    const float* ev   = (const float*)d_in[3];
    const void*  er   = d_in[4];
    const void*  ec   = d_in[5];
    float* out = (float*)d_out;

    probe_zero<<<(N_NODES + 255) / 256, 256>>>((const int*)er, (const int*)ec);

    // CSR build
    hist_rows<<<(N_EDGES + 255) / 256, 256>>>(er);
    scan_local<<<SCAN_BLOCKS, 1024>>>();
    scan_offsets<<<1, 32>>>();
    scan_add<<<SCAN_BLOCKS, 1024>>>();
    bucket_edges<<<(N_EDGES + 255) / 256, 256>>>(ev, er, ec);

    // splits + GEMM
    split_w<<<(D * D + 255) / 256, 256>>>(w);
    split_x<<<(N_NODES * D / 4 + 255) / 256, 256>>>(x);
    static const int SMEM_BYTES = 8 * SA * (int)sizeof(__nv_bfloat16); // 81920
    cudaFuncSetAttribute(gemm_bf16split,
                         cudaFuncAttributeMaxDynamicSharedMemorySize, SMEM_BYTES);
    dim3 ggrid(D / 128, (N_NODES + 127) / 128);
    gemm_bf16split<<<ggrid, 256, SMEM_BYTES>>>();

    // gather SpMM + bias
    gather_spmm<<<N_NODES, 128>>>(bias, out);
}

// round 6
// speedup vs baseline: 2.1664x; 1.2028x over previous
#include <cuda_runtime.h>
#include <cuda_bf16.h>
#include <cuda_fp16.h>
#include <cstdint>

#define N_NODES 50000
#define N_EDGES 1600000
#define D 512

// ---------------- device scratch ----------------
__device__ __half        g_hidden_h[(long long)N_NODES * D];  // fp16 hidden
__device__ __nv_bfloat16 g_xhi[(long long)N_NODES * D];
__device__ __nv_bfloat16 g_xlo[(long long)N_NODES * D];
__device__ __nv_bfloat16 g_wThi[D * D];   // [n][k]
__device__ __nv_bfloat16 g_wTlo[D * D];
__device__ int   g_rowstart[N_NODES + 1];
__device__ int   g_cursor[N_NODES];
__device__ int   g_blocksum[64];
__device__ int2  g_epack[N_EDGES];
__device__ int   g_idx_is64;

// ---------------- dtype probe + zero counts ----------------
__global__ void probe_zero(const int* __restrict__ er32, const int* __restrict__ ec32) {
    int i = blockIdx.x * blockDim.x + threadIdx.x;
    if (i < N_NODES) g_cursor[i] = 0;
    if (i == 0) {
        int looks64 = 1;
        for (int j = 0; j < 256; j++) {
            if (er32[2 * j + 1] != 0) { looks64 = 0; break; }
            if (ec32[2 * j + 1] != 0) { looks64 = 0; break; }
        }
        g_idx_is64 = looks64;
    }
}

__device__ __forceinline__ int load_idx(const void* p, int e, int is64) {
    long long v;
    if (is64) v = ((const long long*)p)[e];
    else      v = ((const int*)p)[e];
    if (v < 0) v = 0;
    if (v >= N_NODES) v = N_NODES - 1;
    return (int)v;
}

// ---------------- bf16 splits ----------------
__global__ void split_w(const float* __restrict__ w) {
    int idx = blockIdx.x * blockDim.x + threadIdx.x;
    if (idx >= D * D) return;
    int k = idx >> 9, n = idx & 511;
    float v = w[idx];
    __nv_bfloat16 hi = __float2bfloat16(v);
    g_wThi[n * D + k] = hi;
    g_wTlo[n * D + k] = __float2bfloat16(v - __bfloat162float(hi));
}

__global__ void split_x(const float* __restrict__ x) {
    long long i = (long long)(blockIdx.x * blockDim.x + threadIdx.x) * 4;
    if (i >= (long long)N_NODES * D) return;
    float4 v = *(const float4*)(x + i);
    __nv_bfloat16 h0 = __float2bfloat16(v.x), h1 = __float2bfloat16(v.y);
    __nv_bfloat16 h2 = __float2bfloat16(v.z), h3 = __float2bfloat16(v.w);
    __nv_bfloat16 l0 = __float2bfloat16(v.x - __bfloat162float(h0));
    __nv_bfloat16 l1 = __float2bfloat16(v.y - __bfloat162float(h1));
    __nv_bfloat16 l2 = __float2bfloat16(v.z - __bfloat162float(h2));
    __nv_bfloat16 l3 = __float2bfloat16(v.w - __bfloat162float(h3));
    __nv_bfloat162* ph = (__nv_bfloat162*)(g_xhi + i);
    __nv_bfloat162* pl = (__nv_bfloat162*)(g_xlo + i);
    ph[0] = __nv_bfloat162(h0, h1); ph[1] = __nv_bfloat162(h2, h3);
    pl[0] = __nv_bfloat162(l0, l1); pl[1] = __nv_bfloat162(l2, l3);
}

// ---------------- tensor-core GEMM (mma.sync, 3-term bf16 split) ----------
#define BK 32
#define ROWPAD 40
#define SA (128 * ROWPAD)

__device__ __forceinline__ void cpa16(uint32_t dst, const void* src) {
    asm volatile("cp.async.cg.shared.global [%0], [%1], 16;\n" :: "r"(dst), "l"(src));
}
__device__ __forceinline__ void cpa_commit() { asm volatile("cp.async.commit_group;\n"); }
template <int N>
__device__ __forceinline__ void cpa_wait() { asm volatile("cp.async.wait_group %0;\n" :: "n"(N)); }

__device__ __forceinline__ void ldsm_x4(uint32_t* r, uint32_t addr) {
    asm volatile("ldmatrix.sync.aligned.m8n8.x4.shared.b16 {%0,%1,%2,%3}, [%4];\n"
                 : "=r"(r[0]), "=r"(r[1]), "=r"(r[2]), "=r"(r[3]) : "r"(addr));
}
__device__ __forceinline__ void ldsm_x2(uint32_t* r, uint32_t addr) {
    asm volatile("ldmatrix.sync.aligned.m8n8.x2.shared.b16 {%0,%1}, [%2];\n"
                 : "=r"(r[0]), "=r"(r[1]) : "r"(addr));
}
__device__ __forceinline__ void mma16816(float* c, const uint32_t* a, const uint32_t* b) {
    asm volatile("mma.sync.aligned.m16n8k16.row.col.f32.bf16.bf16.f32 "
                 "{%0,%1,%2,%3}, {%4,%5,%6,%7}, {%8,%9}, {%0,%1,%2,%3};\n"
                 : "+f"(c[0]), "+f"(c[1]), "+f"(c[2]), "+f"(c[3])
                 : "r"(a[0]), "r"(a[1]), "r"(a[2]), "r"(a[3]), "r"(b[0]), "r"(b[1]));
}

__global__ __launch_bounds__(256, 2) void gemm_bf16split() {
    extern __shared__ __nv_bfloat16 smem[];
    __nv_bfloat16* sAhi = smem;
    __nv_bfloat16* sAlo = smem + 2 * SA;
    __nv_bfloat16* sBhi = smem + 4 * SA;
    __nv_bfloat16* sBlo = smem + 6 * SA;

    const int tid  = threadIdx.x;
    const int lane = tid & 31;
    const int wid  = tid >> 5;
    const int warp_m = wid & 1;
    const int warp_n = wid >> 1;
    const int brow = blockIdx.y * 128;
    const int bcol = blockIdx.x * 128;

    const int lrow  = tid >> 1;
    const int kloc  = (tid & 1) * 16;

    int arow = brow + lrow; if (arow >= N_NODES) arow = N_NODES - 1;
    const int bn = bcol + lrow;

    const __nv_bfloat16* srcAh = g_xhi + (long long)arow * D;
    const __nv_bfloat16* srcAl = g_xlo + (long long)arow * D;
    const __nv_bfloat16* srcBh = g_wThi + bn * D;
    const __nv_bfloat16* srcBl = g_wTlo + bn * D;

    const int dstoff = lrow * ROWPAD + kloc;

    float acc[4][4][4];
    #pragma unroll
    for (int i = 0; i < 4; i++)
        #pragma unroll
        for (int j = 0; j < 4; j++)
            #pragma unroll
            for (int c = 0; c < 4; c++) acc[i][j][c] = 0.f;

    const int NK = D / BK;   // 16

    auto issue_stage = [&](int kt, int st) {
        int k0 = kt * BK + kloc;
        uint32_t dA_hi = (uint32_t)__cvta_generic_to_shared(sAhi + st * SA + dstoff);
        uint32_t dA_lo = (uint32_t)__cvta_generic_to_shared(sAlo + st * SA + dstoff);
        uint32_t dB_hi = (uint32_t)__cvta_generic_to_shared(sBhi + st * SA + dstoff);
        uint32_t dB_lo = (uint32_t)__cvta_generic_to_shared(sBlo + st * SA + dstoff);
        cpa16(dA_hi,      srcAh + k0);
        cpa16(dA_hi + 16, srcAh + k0 + 8);
        cpa16(dA_lo,      srcAl + k0);
        cpa16(dA_lo + 16, srcAl + k0 + 8);
        cpa16(dB_hi,      srcBh + k0);
        cpa16(dB_hi + 16, srcBh + k0 + 8);
        cpa16(dB_lo,      srcBl + k0);
        cpa16(dB_lo + 16, srcBl + k0 + 8);
        cpa_commit();
    };

    issue_stage(0, 0);

    for (int kt = 0; kt < NK; kt++) {
        int st = kt & 1;
        if (kt + 1 < NK) { issue_stage(kt + 1, st ^ 1); cpa_wait<1>(); }
        else             { cpa_wait<0>(); }
        __syncthreads();

        #pragma unroll
        for (int kk = 0; kk < 2; kk++) {
            uint32_t afh[4][4], afl[4][4];
            uint32_t bfh[4][2], bfl[4][2];

            const int arow_t = warp_m * 64 + (lane & 15);
            const int akoff  = kk * 16 + (lane >> 4) * 8;
            #pragma unroll
            for (int mt = 0; mt < 4; mt++) {
                int off = st * SA + (arow_t + mt * 16) * ROWPAD + akoff;
                ldsm_x4(afh[mt], (uint32_t)__cvta_generic_to_shared(sAhi + off));
                ldsm_x4(afl[mt], (uint32_t)__cvta_generic_to_shared(sAlo + off));
            }
            const int brow_t = warp_n * 32 + (lane & 7);
            const int bkoff  = kk * 16 + ((lane >> 3) & 1) * 8;
            #pragma unroll
            for (int nt = 0; nt < 4; nt++) {
                int off = st * SA + (brow_t + nt * 8) * ROWPAD + bkoff;
                ldsm_x2(bfh[nt], (uint32_t)__cvta_generic_to_shared(sBhi + off));
                ldsm_x2(bfl[nt], (uint32_t)__cvta_generic_to_shared(sBlo + off));
            }

            #pragma unroll
            for (int mt = 0; mt < 4; mt++)
                #pragma unroll
                for (int nt = 0; nt < 4; nt++) {
                    mma16816(acc[mt][nt], afh[mt], bfh[nt]);
                    mma16816(acc[mt][nt], afh[mt], bfl[nt]);
                    mma16816(acc[mt][nt], afl[mt], bfh[nt]);
                }
        }
        __syncthreads();
    }

    // epilogue: fp32 acc -> fp16 hidden
    #pragma unroll
    for (int mt = 0; mt < 4; mt++) {
        int row0 = brow + warp_m * 64 + mt * 16 + (lane >> 2);
        #pragma unroll
        for (int nt = 0; nt < 4; nt++) {
            int col = bcol + warp_n * 32 + nt * 8 + (lane & 3) * 2;
            if (row0 < N_NODES)
                *(__half2*)(g_hidden_h + (long long)row0 * D + col) =
                    __floats2half2_rn(acc[mt][nt][0], acc[mt][nt][1]);
            if (row0 + 8 < N_NODES)
                *(__half2*)(g_hidden_h + (long long)(row0 + 8) * D + col) =
                    __floats2half2_rn(acc[mt][nt][2], acc[mt][nt][3]);
        }
    }
}

// ---------------- CSR build ----------------
__global__ void hist_rows(const void* __restrict__ er) {
    int e = blockIdx.x * blockDim.x + threadIdx.x;
    if (e < N_EDGES) atomicAdd(&g_cursor[load_idx(er, e, g_idx_is64)], 1);
}

#define SCAN_BLOCKS ((N_NODES + 1023) / 1024)

__global__ __launch_bounds__(1024) void scan_local() {
    __shared__ int sdata[1024];
    int b = blockIdx.x, t = threadIdx.x;
    int i = b * 1024 + t;
    int v = (i < N_NODES) ? g_cursor[i] : 0;
    sdata[t] = v;
    __syncthreads();
    for (int off = 1; off < 1024; off <<= 1) {
        int tv = (t >= off) ? sdata[t - off] : 0;
        __syncthreads();
        sdata[t] += tv;
        __syncthreads();
    }
    if (i < N_NODES) g_rowstart[i] = sdata[t] - v;
    if (t == 1023) g_blocksum[b] = sdata[1023];
}

__global__ void scan_offsets() {
    if (threadIdx.x == 0) {
        int run = 0;
        for (int j = 0; j < SCAN_BLOCKS; j++) {
            int s = g_blocksum[j];
            g_blocksum[j] = run;
            run += s;
        }
        g_rowstart[N_NODES] = run;
    }
}

__global__ __launch_bounds__(1024) void scan_add() {
    int i = blockIdx.x * 1024 + threadIdx.x;
    if (i < N_NODES) {
        int v = g_rowstart[i] + g_blocksum[blockIdx.x];
        g_rowstart[i] = v;
        g_cursor[i]   = v;
    }
}

__global__ void bucket_edges(const float* __restrict__ ev,
                             const void* __restrict__ er,
                             const void* __restrict__ ec) {
    int e = blockIdx.x * blockDim.x + threadIdx.x;
    if (e < N_EDGES) {
        int is64 = g_idx_is64;
        int row = load_idx(er, e, is64);
        int col = load_idx(ec, e, is64);
        int pos = atomicAdd(&g_cursor[row], 1);
        if (pos >= 0 && pos < N_EDGES)
            g_epack[pos] = make_int2(col, __float_as_int(ev[e]));
    }
}

// ---------------- gather SpMM (fp16 hidden, fp32 accumulate) -------------
__global__ __launch_bounds__(128) void gather_spmm(const float* __restrict__ bias,
                                                   float* __restrict__ out) {
    const int node  = blockIdx.x;
    const int start = g_rowstart[node];
    const int end   = g_rowstart[node + 1];

    __shared__ int2 s_e[512];
    const __half2* __restrict__ H2 = (const __half2*)g_hidden_h;
    const int tid = threadIdx.x;

    float4 acc = make_float4(0.f, 0.f, 0.f, 0.f);

    for (int base = start; base < end; base += 512) {
        int cnt = min(end - base, 512);
        for (int i = tid; i < cnt; i += 128)
            s_e[i] = g_epack[base + i];
        __syncthreads();
        for (int i = 0; i < cnt; i++) {
            int2 p = s_e[i];
            float v = __int_as_float(p.y);
            long long hb = (long long)p.x * (D / 2) + tid * 2;
            __half2 a = H2[hb];
            __half2 b = H2[hb + 1];
            float2 fa = __half22float2(a);
            float2 fb = __half22float2(b);
            acc.x += v * fa.x; acc.y += v * fa.y;
            acc.z += v * fb.x; acc.w += v * fb.y;
        }
        __syncthreads();
    }

    float4 bv = ((const float4*)bias)[tid];
    acc.x += bv.x; acc.y += bv.y; acc.z += bv.z; acc.w += bv.w;
    ((float4*)out)[(long long)node * (D / 4) + tid] = acc;
}

// ---------------- launcher ----------------
extern "C" void kernel_launch(void* const* d_in, const int* in_sizes, int n_in,
                              void* d_out, int out_size) {
    const float* x    = (const float*)d_in[0];
    const float* w    = (const float*)d_in[1];
    const float* bias = (const float*)d_in[2];
    const float* ev   = (const float*)d_in[3];
    const void*  er   = d_in[4];
    const void*  ec   = d_in[5];
    float* out = (float*)d_out;

    probe_zero<<<(N_NODES + 255) / 256, 256>>>((const int*)er, (const int*)ec);

    // CSR build
    hist_rows<<<(N_EDGES + 255) / 256, 256>>>(er);
    scan_local<<<SCAN_BLOCKS, 1024>>>();
    scan_offsets<<<1, 32>>>();
    scan_add<<<SCAN_BLOCKS, 1024>>>();
    bucket_edges<<<(N_EDGES + 255) / 256, 256>>>(ev, er, ec);

    // splits + GEMM
    split_w<<<(D * D + 255) / 256, 256>>>(w);
    split_x<<<(N_NODES * D / 4 + 255) / 256, 256>>>(x);
    static const int SMEM_BYTES = 8 * SA * (int)sizeof(__nv_bfloat16); // 81920
    cudaFuncSetAttribute(gemm_bf16split,
                         cudaFuncAttributeMaxDynamicSharedMemorySize, SMEM_BYTES);
    dim3 ggrid(D / 128, (N_NODES + 127) / 128);
    gemm_bf16split<<<ggrid, 256, SMEM_BYTES>>>();

    // gather SpMM + bias
    gather_spmm<<<N_NODES, 128>>>(bias, out);
}

// round 7
// speedup vs baseline: 3.1824x; 1.4690x over previous
#include <cuda_runtime.h>
#include <cuda_fp16.h>
#include <cstdint>

#define N_NODES 50000
#define N_EDGES 1600000
#define D 512

// ---------------- device scratch ----------------
__device__ __half g_hidden_h[(long long)N_NODES * D];  // fp16 hidden
__device__ __half g_xh[(long long)N_NODES * D];        // fp16 x
__device__ __half g_wTh[D * D];                        // fp16 w^T [n][k]
__device__ int   g_rowstart[N_NODES + 1];
__device__ int   g_cursor[N_NODES];
__device__ int   g_blocksum[64];
__device__ int2  g_epack[N_EDGES];
__device__ int   g_idx_is64;

// ---------------- dtype probe + zero counts ----------------
__global__ void probe_zero(const int* __restrict__ er32, const int* __restrict__ ec32) {
    int i = blockIdx.x * blockDim.x + threadIdx.x;
    if (i < N_NODES) g_cursor[i] = 0;
    if (i == 0) {
        int looks64 = 1;
        for (int j = 0; j < 256; j++) {
            if (er32[2 * j + 1] != 0) { looks64 = 0; break; }
            if (ec32[2 * j + 1] != 0) { looks64 = 0; break; }
        }
        g_idx_is64 = looks64;
    }
}

__device__ __forceinline__ int load_idx(const void* p, int e, int is64) {
    long long v;
    if (is64) v = ((const long long*)p)[e];
    else      v = ((const int*)p)[e];
    if (v < 0) v = 0;
    if (v >= N_NODES) v = N_NODES - 1;
    return (int)v;
}

// ---------------- fp16 converts ----------------
__global__ void conv_w(const float* __restrict__ w) {
    int idx = blockIdx.x * blockDim.x + threadIdx.x;
    if (idx >= D * D) return;
    int k = idx >> 9, n = idx & 511;
    g_wTh[n * D + k] = __float2half_rn(w[idx]);   // w[k][n] -> wT[n][k]
}

__global__ void conv_x(const float* __restrict__ x) {
    long long i = (long long)(blockIdx.x * blockDim.x + threadIdx.x) * 4;
    if (i >= (long long)N_NODES * D) return;
    float4 v = *(const float4*)(x + i);
    __half2* ph = (__half2*)(g_xh + i);
    ph[0] = __floats2half2_rn(v.x, v.y);
    ph[1] = __floats2half2_rn(v.z, v.w);
}

// ---------------- tensor-core GEMM (single fp16 mma.sync) ----------------
#define BK 32
#define ROWPAD 40
#define SA (128 * ROWPAD)

__device__ __forceinline__ void cpa16(uint32_t dst, const void* src) {
    asm volatile("cp.async.cg.shared.global [%0], [%1], 16;\n" :: "r"(dst), "l"(src));
}
__device__ __forceinline__ void cpa_commit() { asm volatile("cp.async.commit_group;\n"); }
template <int N>
__device__ __forceinline__ void cpa_wait() { asm volatile("cp.async.wait_group %0;\n" :: "n"(N)); }

__device__ __forceinline__ void ldsm_x4(uint32_t* r, uint32_t addr) {
    asm volatile("ldmatrix.sync.aligned.m8n8.x4.shared.b16 {%0,%1,%2,%3}, [%4];\n"
                 : "=r"(r[0]), "=r"(r[1]), "=r"(r[2]), "=r"(r[3]) : "r"(addr));
}
__device__ __forceinline__ void ldsm_x2(uint32_t* r, uint32_t addr) {
    asm volatile("ldmatrix.sync.aligned.m8n8.x2.shared.b16 {%0,%1}, [%2];\n"
                 : "=r"(r[0]), "=r"(r[1]) : "r"(addr));
}
__device__ __forceinline__ void mma16816(float* c, const uint32_t* a, const uint32_t* b) {
    asm volatile("mma.sync.aligned.m16n8k16.row.col.f32.f16.f16.f32 "
                 "{%0,%1,%2,%3}, {%4,%5,%6,%7}, {%8,%9}, {%0,%1,%2,%3};\n"
                 : "+f"(c[0]), "+f"(c[1]), "+f"(c[2]), "+f"(c[3])
                 : "r"(a[0]), "r"(a[1]), "r"(a[2]), "r"(a[3]), "r"(b[0]), "r"(b[1]));
}

__global__ __launch_bounds__(256, 2) void gemm_fp16() {
    extern __shared__ __half smem[];
    __half* sA = smem;                 // 2 stages
    __half* sB = smem + 2 * SA;        // 2 stages

    const int tid  = threadIdx.x;
    const int lane = tid & 31;
    const int wid  = tid >> 5;
    const int warp_m = wid & 1;
    const int warp_n = wid >> 1;
    const int brow = blockIdx.y * 128;
    const int bcol = blockIdx.x * 128;

    const int lrow  = tid >> 1;
    const int kloc  = (tid & 1) * 16;

    int arow = brow + lrow; if (arow >= N_NODES) arow = N_NODES - 1;
    const int bn = bcol + lrow;

    const __half* srcA = g_xh  + (long long)arow * D;
    const __half* srcB = g_wTh + bn * D;

    const int dstoff = lrow * ROWPAD + kloc;

    float acc[4][4][4];
    #pragma unroll
    for (int i = 0; i < 4; i++)
        #pragma unroll
        for (int j = 0; j < 4; j++)
            #pragma unroll
            for (int c = 0; c < 4; c++) acc[i][j][c] = 0.f;

    const int NK = D / BK;   // 16

    auto issue_stage = [&](int kt, int st) {
        int k0 = kt * BK + kloc;
        uint32_t dA = (uint32_t)__cvta_generic_to_shared(sA + st * SA + dstoff);
        uint32_t dB = (uint32_t)__cvta_generic_to_shared(sB + st * SA + dstoff);
        cpa16(dA,      srcA + k0);
        cpa16(dA + 16, srcA + k0 + 8);
        cpa16(dB,      srcB + k0);
        cpa16(dB + 16, srcB + k0 + 8);
        cpa_commit();
    };

    issue_stage(0, 0);

    for (int kt = 0; kt < NK; kt++) {
        int st = kt & 1;
        if (kt + 1 < NK) { issue_stage(kt + 1, st ^ 1); cpa_wait<1>(); }
        else             { cpa_wait<0>(); }
        __syncthreads();

        #pragma unroll
        for (int kk = 0; kk < 2; kk++) {
            uint32_t af[4][4];
            uint32_t bf[4][2];

            const int arow_t = warp_m * 64 + (lane & 15);
            const int akoff  = kk * 16 + (lane >> 4) * 8;
            #pragma unroll
            for (int mt = 0; mt < 4; mt++) {
                int off = st * SA + (arow_t + mt * 16) * ROWPAD + akoff;
                ldsm_x4(af[mt], (uint32_t)__cvta_generic_to_shared(sA + off));
            }
            const int brow_t = warp_n * 32 + (lane & 7);
            const int bkoff  = kk * 16 + ((lane >> 3) & 1) * 8;
            #pragma unroll
            for (int nt = 0; nt < 4; nt++) {
                int off = st * SA + (brow_t + nt * 8) * ROWPAD + bkoff;
                ldsm_x2(bf[nt], (uint32_t)__cvta_generic_to_shared(sB + off));
            }

            #pragma unroll
            for (int mt = 0; mt < 4; mt++)
                #pragma unroll
                for (int nt = 0; nt < 4; nt++)
                    mma16816(acc[mt][nt], af[mt], bf[nt]);
        }
        __syncthreads();
    }

    // epilogue: fp32 acc -> fp16 hidden
    #pragma unroll
    for (int mt = 0; mt < 4; mt++) {
        int row0 = brow + warp_m * 64 + mt * 16 + (lane >> 2);
        #pragma unroll
        for (int nt = 0; nt < 4; nt++) {
            int col = bcol + warp_n * 32 + nt * 8 + (lane & 3) * 2;
            if (row0 < N_NODES)
                *(__half2*)(g_hidden_h + (long long)row0 * D + col) =
                    __floats2half2_rn(acc[mt][nt][0], acc[mt][nt][1]);
            if (row0 + 8 < N_NODES)
                *(__half2*)(g_hidden_h + (long long)(row0 + 8) * D + col) =
                    __floats2half2_rn(acc[mt][nt][2], acc[mt][nt][3]);
        }
    }
}

// ---------------- CSR build ----------------
__global__ void hist_rows(const void* __restrict__ er) {
    int e = blockIdx.x * blockDim.x + threadIdx.x;
    if (e < N_EDGES) atomicAdd(&g_cursor[load_idx(er, e, g_idx_is64)], 1);
}

#define SCAN_BLOCKS ((N_NODES + 1023) / 1024)

__global__ __launch_bounds__(1024) void scan_local() {
    __shared__ int sdata[1024];
    int b = blockIdx.x, t = threadIdx.x;
    int i = b * 1024 + t;
    int v = (i < N_NODES) ? g_cursor[i] : 0;
    sdata[t] = v;
    __syncthreads();
    for (int off = 1; off < 1024; off <<= 1) {
        int tv = (t >= off) ? sdata[t - off] : 0;
        __syncthreads();
        sdata[t] += tv;
        __syncthreads();
    }
    if (i < N_NODES) g_rowstart[i] = sdata[t] - v;
    if (t == 1023) g_blocksum[b] = sdata[1023];
}

__global__ void scan_offsets() {
    if (threadIdx.x == 0) {
        int run = 0;
        for (int j = 0; j < SCAN_BLOCKS; j++) {
            int s = g_blocksum[j];
            g_blocksum[j] = run;
            run += s;
        }
        g_rowstart[N_NODES] = run;
    }
}

__global__ __launch_bounds__(1024) void scan_add() {
    int i = blockIdx.x * 1024 + threadIdx.x;
    if (i < N_NODES) {
        int v = g_rowstart[i] + g_blocksum[blockIdx.x];
        g_rowstart[i] = v;
        g_cursor[i]   = v;
    }
}

__global__ void bucket_edges(const float* __restrict__ ev,
                             const void* __restrict__ er,
                             const void* __restrict__ ec) {
    int e = blockIdx.x * blockDim.x + threadIdx.x;
    if (e < N_EDGES) {
        int is64 = g_idx_is64;
        int row = load_idx(er, e, is64);
        int col = load_idx(ec, e, is64);
        int pos = atomicAdd(&g_cursor[row], 1);
        if (pos >= 0 && pos < N_EDGES)
            g_epack[pos] = make_int2(col, __float_as_int(ev[e]));
    }
}

// ---------------- gather SpMM (fp16 hidden, fp32 accumulate) -------------
__global__ __launch_bounds__(128) void gather_spmm(const float* __restrict__ bias,
                                                   float* __restrict__ out) {
    const int node  = blockIdx.x;
    const int start = g_rowstart[node];
    const int end   = g_rowstart[node + 1];

    __shared__ int2 s_e[512];
    const __half2* __restrict__ H2 = (const __half2*)g_hidden_h;
    const int tid = threadIdx.x;

    float4 acc = make_float4(0.f, 0.f, 0.f, 0.f);

    for (int base = start; base < end; base += 512) {
        int cnt = min(end - base, 512);
        for (int i = tid; i < cnt; i += 128)
            s_e[i] = g_epack[base + i];
        __syncthreads();
        for (int i = 0; i < cnt; i++) {
            int2 p = s_e[i];
            float v = __int_as_float(p.y);
            long long hb = (long long)p.x * (D / 2) + tid * 2;
            __half2 a = H2[hb];
            __half2 b = H2[hb + 1];
            float2 fa = __half22float2(a);
            float2 fb = __half22float2(b);
            acc.x += v * fa.x; acc.y += v * fa.y;
            acc.z += v * fb.x; acc.w += v * fb.y;
        }
        __syncthreads();
    }

    float4 bv = ((const float4*)bias)[tid];
    acc.x += bv.x; acc.y += bv.y; acc.z += bv.z; acc.w += bv.w;
    ((float4*)out)[(long long)node * (D / 4) + tid] = acc;
}

// ---------------- launcher ----------------
extern "C" void kernel_launch(void* const* d_in, const int* in_sizes, int n_in,
                              void* d_out, int out_size) {
    const float* x    = (const float*)d_in[0];
    const float* w    = (const float*)d_in[1];
    const float* bias = (const float*)d_in[2];
    const float* ev   = (const float*)d_in[3];
    const void*  er   = d_in[4];
    const void*  ec   = d_in[5];
    float* out = (float*)d_out;

    probe_zero<<<(N_NODES + 255) / 256, 256>>>((const int*)er, (const int*)ec);

    // CSR build
    hist_rows<<<(N_EDGES + 255) / 256, 256>>>(er);
    scan_local<<<SCAN_BLOCKS, 1024>>>();
    scan_offsets<<<1, 32>>>();
    scan_add<<<SCAN_BLOCKS, 1024>>>();
    bucket_edges<<<(N_EDGES + 255) / 256, 256>>>(ev, er, ec);

    // converts + GEMM
    conv_w<<<(D * D + 255) / 256, 256>>>(w);
    conv_x<<<(N_NODES * D / 4 + 255) / 256, 256>>>(x);
    static const int SMEM_BYTES = 4 * SA * (int)sizeof(__half); // 40960
    cudaFuncSetAttribute(gemm_fp16,
                         cudaFuncAttributeMaxDynamicSharedMemorySize, SMEM_BYTES);
    dim3 ggrid(D / 128, (N_NODES + 127) / 128);
    gemm_fp16<<<ggrid, 256, SMEM_BYTES>>>();

    // gather SpMM + bias
    gather_spmm<<<N_NODES, 128>>>(bias, out);
}

// round 8
// speedup vs baseline: 3.3564x; 1.0547x over previous
#include <cuda_runtime.h>
#include <cuda_fp16.h>
#include <cstdint>

#define N_NODES 50000
#define N_EDGES 1600000
#define D 512

// ---------------- device scratch ----------------
__device__ __half g_hidden_h[(long long)N_NODES * D];  // fp16 hidden
__device__ __half g_xh[(long long)N_NODES * D];        // fp16 x
__device__ __half g_wTh[D * D];                        // fp16 w^T [n][k]
__device__ int   g_rowstart[N_NODES + 1];
__device__ int   g_cursor[N_NODES];
__device__ int   g_blocksum[64];
__device__ int2  g_epack[N_EDGES];
__device__ int   g_idx_is64;

// ---------------- dtype probe + zero counts ----------------
__global__ void probe_zero(const int* __restrict__ er32, const int* __restrict__ ec32) {
    int i = blockIdx.x * blockDim.x + threadIdx.x;
    if (i < N_NODES) g_cursor[i] = 0;
    if (i == 0) {
        int looks64 = 1;
        for (int j = 0; j < 256; j++) {
            if (er32[2 * j + 1] != 0) { looks64 = 0; break; }
            if (ec32[2 * j + 1] != 0) { looks64 = 0; break; }
        }
        g_idx_is64 = looks64;
    }
}

__device__ __forceinline__ int load_idx(const void* p, int e, int is64) {
    long long v;
    if (is64) v = ((const long long*)p)[e];
    else      v = ((const int*)p)[e];
    if (v < 0) v = 0;
    if (v >= N_NODES) v = N_NODES - 1;
    return (int)v;
}

// ---------------- fp16 converts ----------------
__global__ void conv_w(const float* __restrict__ w) {
    int idx = blockIdx.x * blockDim.x + threadIdx.x;
    if (idx >= D * D) return;
    int k = idx >> 9, n = idx & 511;
    g_wTh[n * D + k] = __float2half_rn(w[idx]);   // w[k][n] -> wT[n][k]
}

__global__ void conv_x(const float* __restrict__ x) {
    long long i = (long long)(blockIdx.x * blockDim.x + threadIdx.x) * 4;
    if (i >= (long long)N_NODES * D) return;
    float4 v = *(const float4*)(x + i);
    __half2* ph = (__half2*)(g_xh + i);
    ph[0] = __floats2half2_rn(v.x, v.y);
    ph[1] = __floats2half2_rn(v.z, v.w);
}

// ---------------- tensor-core GEMM (single fp16 mma.sync) ----------------
#define BK 32
#define ROWPAD 40
#define SA (128 * ROWPAD)

__device__ __forceinline__ void cpa16(uint32_t dst, const void* src) {
    asm volatile("cp.async.cg.shared.global [%0], [%1], 16;\n" :: "r"(dst), "l"(src));
}
__device__ __forceinline__ void cpa_commit() { asm volatile("cp.async.commit_group;\n"); }
template <int N>
__device__ __forceinline__ void cpa_wait() { asm volatile("cp.async.wait_group %0;\n" :: "n"(N)); }

__device__ __forceinline__ void ldsm_x4(uint32_t* r, uint32_t addr) {
    asm volatile("ldmatrix.sync.aligned.m8n8.x4.shared.b16 {%0,%1,%2,%3}, [%4];\n"
                 : "=r"(r[0]), "=r"(r[1]), "=r"(r[2]), "=r"(r[3]) : "r"(addr));
}
__device__ __forceinline__ void ldsm_x2(uint32_t* r, uint32_t addr) {
    asm volatile("ldmatrix.sync.aligned.m8n8.x2.shared.b16 {%0,%1}, [%2];\n"
                 : "=r"(r[0]), "=r"(r[1]) : "r"(addr));
}
__device__ __forceinline__ void mma16816(float* c, const uint32_t* a, const uint32_t* b) {
    asm volatile("mma.sync.aligned.m16n8k16.row.col.f32.f16.f16.f32 "
                 "{%0,%1,%2,%3}, {%4,%5,%6,%7}, {%8,%9}, {%0,%1,%2,%3};\n"
                 : "+f"(c[0]), "+f"(c[1]), "+f"(c[2]), "+f"(c[3])
                 : "r"(a[0]), "r"(a[1]), "r"(a[2]), "r"(a[3]), "r"(b[0]), "r"(b[1]));
}

__global__ __launch_bounds__(256, 2) void gemm_fp16() {
    extern __shared__ __half smem[];
    __half* sA = smem;
    __half* sB = smem + 2 * SA;

    const int tid  = threadIdx.x;
    const int lane = tid & 31;
    const int wid  = tid >> 5;
    const int warp_m = wid & 1;
    const int warp_n = wid >> 1;
    const int brow = blockIdx.y * 128;
    const int bcol = blockIdx.x * 128;

    const int lrow  = tid >> 1;
    const int kloc  = (tid & 1) * 16;

    int arow = brow + lrow; if (arow >= N_NODES) arow = N_NODES - 1;
    const int bn = bcol + lrow;

    const __half* srcA = g_xh  + (long long)arow * D;
    const __half* srcB = g_wTh + bn * D;

    const int dstoff = lrow * ROWPAD + kloc;

    float acc[4][4][4];
    #pragma unroll
    for (int i = 0; i < 4; i++)
        #pragma unroll
        for (int j = 0; j < 4; j++)
            #pragma unroll
            for (int c = 0; c < 4; c++) acc[i][j][c] = 0.f;

    const int NK = D / BK;   // 16

    auto issue_stage = [&](int kt, int st) {
        int k0 = kt * BK + kloc;
        uint32_t dA = (uint32_t)__cvta_generic_to_shared(sA + st * SA + dstoff);
        uint32_t dB = (uint32_t)__cvta_generic_to_shared(sB + st * SA + dstoff);
        cpa16(dA,      srcA + k0);
        cpa16(dA + 16, srcA + k0 + 8);
        cpa16(dB,      srcB + k0);
        cpa16(dB + 16, srcB + k0 + 8);
        cpa_commit();
    };

    issue_stage(0, 0);

    for (int kt = 0; kt < NK; kt++) {
        int st = kt & 1;
        if (kt + 1 < NK) { issue_stage(kt + 1, st ^ 1); cpa_wait<1>(); }
        else             { cpa_wait<0>(); }
        __syncthreads();

        #pragma unroll
        for (int kk = 0; kk < 2; kk++) {
            uint32_t af[4][4];
            uint32_t bf[4][2];

            const int arow_t = warp_m * 64 + (lane & 15);
            const int akoff  = kk * 16 + (lane >> 4) * 8;
            #pragma unroll
            for (int mt = 0; mt < 4; mt++) {
                int off = st * SA + (arow_t + mt * 16) * ROWPAD + akoff;
                ldsm_x4(af[mt], (uint32_t)__cvta_generic_to_shared(sA + off));
            }
            const int brow_t = warp_n * 32 + (lane & 7);
            const int bkoff  = kk * 16 + ((lane >> 3) & 1) * 8;
            #pragma unroll
            for (int nt = 0; nt < 4; nt++) {
                int off = st * SA + (brow_t + nt * 8) * ROWPAD + bkoff;
                ldsm_x2(bf[nt], (uint32_t)__cvta_generic_to_shared(sB + off));
            }

            #pragma unroll
            for (int mt = 0; mt < 4; mt++)
                #pragma unroll
                for (int nt = 0; nt < 4; nt++)
                    mma16816(acc[mt][nt], af[mt], bf[nt]);
        }
        __syncthreads();
    }

    #pragma unroll
    for (int mt = 0; mt < 4; mt++) {
        int row0 = brow + warp_m * 64 + mt * 16 + (lane >> 2);
        #pragma unroll
        for (int nt = 0; nt < 4; nt++) {
            int col = bcol + warp_n * 32 + nt * 8 + (lane & 3) * 2;
            if (row0 < N_NODES)
                *(__half2*)(g_hidden_h + (long long)row0 * D + col) =
                    __floats2half2_rn(acc[mt][nt][0], acc[mt][nt][1]);
            if (row0 + 8 < N_NODES)
                *(__half2*)(g_hidden_h + (long long)(row0 + 8) * D + col) =
                    __floats2half2_rn(acc[mt][nt][2], acc[mt][nt][3]);
        }
    }
}

// ---------------- CSR build ----------------
__global__ void hist_rows(const void* __restrict__ er) {
    int e = blockIdx.x * blockDim.x + threadIdx.x;
    if (e < N_EDGES) atomicAdd(&g_cursor[load_idx(er, e, g_idx_is64)], 1);
}

#define SCAN_BLOCKS ((N_NODES + 1023) / 1024)

__global__ __launch_bounds__(1024) void scan_local() {
    __shared__ int sdata[1024];
    int b = blockIdx.x, t = threadIdx.x;
    int i = b * 1024 + t;
    int v = (i < N_NODES) ? g_cursor[i] : 0;
    sdata[t] = v;
    __syncthreads();
    for (int off = 1; off < 1024; off <<= 1) {
        int tv = (t >= off) ? sdata[t - off] : 0;
        __syncthreads();
        sdata[t] += tv;
        __syncthreads();
    }
    if (i < N_NODES) g_rowstart[i] = sdata[t] - v;
    if (t == 1023) g_blocksum[b] = sdata[1023];
}

__global__ void scan_offsets() {
    if (threadIdx.x == 0) {
        int run = 0;
        for (int j = 0; j < SCAN_BLOCKS; j++) {
            int s = g_blocksum[j];
            g_blocksum[j] = run;
            run += s;
        }
        g_rowstart[N_NODES] = run;
    }
}

__global__ __launch_bounds__(1024) void scan_add() {
    int i = blockIdx.x * 1024 + threadIdx.x;
    if (i < N_NODES) {
        int v = g_rowstart[i] + g_blocksum[blockIdx.x];
        g_rowstart[i] = v;
        g_cursor[i]   = v;
    }
}

__global__ void bucket_edges(const float* __restrict__ ev,
                             const void* __restrict__ er,
                             const void* __restrict__ ec) {
    int e = blockIdx.x * blockDim.x + threadIdx.x;
    if (e < N_EDGES) {
        int is64 = g_idx_is64;
        int row = load_idx(er, e, is64);
        int col = load_idx(ec, e, is64);
        int pos = atomicAdd(&g_cursor[row], 1);
        if (pos >= 0 && pos < N_EDGES)
            g_epack[pos] = make_int2(col, __float_as_int(ev[e]));
    }
}

// ---------------- gather SpMM (fp16 hidden, fp32 accumulate) -------------
__global__ __launch_bounds__(128) void gather_spmm(const float* __restrict__ bias,
                                                   float* __restrict__ out) {
    const int node  = blockIdx.x;
    const int start = g_rowstart[node];
    const int end   = g_rowstart[node + 1];

    __shared__ int2 s_e[512];
    const __half2* __restrict__ H2 = (const __half2*)g_hidden_h;
    const int tid = threadIdx.x;

    float4 acc = make_float4(0.f, 0.f, 0.f, 0.f);

    for (int base = start; base < end; base += 512) {
        int cnt = min(end - base, 512);
        for (int i = tid; i < cnt; i += 128)
            s_e[i] = g_epack[base + i];
        __syncthreads();
        for (int i = 0; i < cnt; i++) {
            int2 p = s_e[i];
            float v = __int_as_float(p.y);
            long long hb = (long long)p.x * (D / 2) + tid * 2;
            __half2 a = H2[hb];
            __half2 b = H2[hb + 1];
            float2 fa = __half22float2(a);
            float2 fb = __half22float2(b);
            acc.x += v * fa.x; acc.y += v * fa.y;
            acc.z += v * fb.x; acc.w += v * fb.y;
        }
        __syncthreads();
    }

    float4 bv = ((const float4*)bias)[tid];
    acc.x += bv.x; acc.y += bv.y; acc.z += bv.z; acc.w += bv.w;
    ((float4*)out)[(long long)node * (D / 4) + tid] = acc;
}

// ---------------- launcher (fork/join two independent chains) ------------
extern "C" void kernel_launch(void* const* d_in, const int* in_sizes, int n_in,
                              void* d_out, int out_size) {
    const float* x    = (const float*)d_in[0];
    const float* w    = (const float*)d_in[1];
    const float* bias = (const float*)d_in[2];
    const float* ev   = (const float*)d_in[3];
    const void*  er   = d_in[4];
    const void*  ec   = d_in[5];
    float* out = (float*)d_out;

    // one-time host-side infra (no device memory involved)
    static cudaStream_t s_side = nullptr;
    static cudaEvent_t  ev_fork = nullptr, ev_join = nullptr;
    if (s_side == nullptr) {
        cudaStreamCreateWithFlags(&s_side, cudaStreamNonBlocking);
        cudaEventCreateWithFlags(&ev_fork, cudaEventDisableTiming);
        cudaEventCreateWithFlags(&ev_join, cudaEventDisableTiming);
        cudaFuncSetAttribute(gemm_fp16,
                             cudaFuncAttributeMaxDynamicSharedMemorySize,
                             4 * SA * (int)sizeof(__half));
    }

    // fork side stream off the (capture-origin) default stream
    cudaEventRecord(ev_fork, 0);
    cudaStreamWaitEvent(s_side, ev_fork, 0);

    // ---- side chain: converts + GEMM (depends only on x, w) ----
    conv_w<<<(D * D + 255) / 256, 256, 0, s_side>>>(w);
    conv_x<<<(N_NODES * D / 4 + 255) / 256, 256, 0, s_side>>>(x);
    dim3 ggrid(D / 128, (N_NODES + 127) / 128);
    gemm_fp16<<<ggrid, 256, 4 * SA * (int)sizeof(__half), s_side>>>();
    cudaEventRecord(ev_join, s_side);

    // ---- main chain: CSR build (depends only on edges) ----
    probe_zero<<<(N_NODES + 255) / 256, 256>>>((const int*)er, (const int*)ec);
    hist_rows<<<(N_EDGES + 255) / 256, 256>>>(er);
    scan_local<<<SCAN_BLOCKS, 1024>>>();
    scan_offsets<<<1, 32>>>();
    scan_add<<<SCAN_BLOCKS, 1024>>>();
    bucket_edges<<<(N_EDGES + 255) / 256, 256>>>(ev, er, ec);

    // join, then gather needs both hidden and CSR
    cudaStreamWaitEvent(0, ev_join, 0);
    gather_spmm<<<N_NODES, 128>>>(bias, out);
}